// round 3
// baseline (speedup 1.0000x reference)
#include <cuda_runtime.h>
#include <math.h>

// Problem dims
constexpr int S  = 2048;
constexpr int E  = 2048;
constexpr int H  = 16;
constexpr int KD = 128;   // E/H
constexpr int FF = 8192;  // 4*E
constexpr float EPS = 1e-5f;
constexpr long NTOT = (long)S * E;

// ---------------- scratch (device globals; no allocations allowed) ----------
__device__ float  g_q [(long)H * S * KD];   // 16 MB
__device__ float  g_k [(long)H * S * KD];   // 16 MB
__device__ float  g_v [(long)H * S * E];    // 256 MB
__device__ float  g_sc[(long)H * S * S];    // 256 MB (scores -> attn in place)
__device__ float  g_y [(long)S * E];        // residual sums
__device__ float  g_h [(long)S * E];        // post-LN1 activations
__device__ float  g_ff[(long)S * FF];       // 64 MB
__device__ double g_part[2 * 1024];
__device__ float  g_stats[2];

// ---------------- tiled fp32 GEMM: C = A[M,K] @ B[K,N] (+bias)(+resid)(relu) --
// 128x128 tile, BK=16, 256 threads, 8x8 per thread. All dims multiples of 128/16.
#define BMT 128
#define BNT 128
#define BKT 16

__global__ __launch_bounds__(256) void gemm_nn(
    const float* __restrict__ A, const float* __restrict__ Bg,
    const float* __restrict__ bias, const float* __restrict__ resid,
    float* __restrict__ Cg, int M, int N, int K,
    long sB, long sBias, long sC, int relu)
{
    const float* B  = Bg + (long)blockIdx.z * sB;
    const float* bi = bias ? bias + (long)blockIdx.z * sBias : nullptr;
    float*       C  = Cg + (long)blockIdx.z * sC;

    __shared__ float As[BKT][BMT];
    __shared__ float Bs[BKT][BNT];

    const int tid  = threadIdx.x;
    const long row0 = (long)blockIdx.y * BMT;
    const long col0 = (long)blockIdx.x * BNT;
    const int arow = tid >> 1, avec = (tid & 1) * 8;   // A tile: 128 rows x 16 k
    const int brow = tid >> 4, bcol = (tid & 15) * 8;  // B tile: 16 k x 128 cols
    const int ty = tid >> 4, tx = tid & 15;

    float acc[8][8] = {};

    for (int k0 = 0; k0 < K; k0 += BKT) {
        const float* ap = A + (row0 + arow) * (long)K + k0 + avec;
        float4 a0 = *(const float4*)(ap);
        float4 a1 = *(const float4*)(ap + 4);
        As[avec + 0][arow] = a0.x; As[avec + 1][arow] = a0.y;
        As[avec + 2][arow] = a0.z; As[avec + 3][arow] = a0.w;
        As[avec + 4][arow] = a1.x; As[avec + 5][arow] = a1.y;
        As[avec + 6][arow] = a1.z; As[avec + 7][arow] = a1.w;
        const float* bp = B + (long)(k0 + brow) * N + col0 + bcol;
        *(float4*)&Bs[brow][bcol + 0] = *(const float4*)(bp);
        *(float4*)&Bs[brow][bcol + 4] = *(const float4*)(bp + 4);
        __syncthreads();
        #pragma unroll
        for (int kk = 0; kk < BKT; kk++) {
            float4 av0 = *(const float4*)&As[kk][ty * 8];
            float4 av1 = *(const float4*)&As[kk][ty * 8 + 4];
            float4 bv0 = *(const float4*)&Bs[kk][tx * 8];
            float4 bv1 = *(const float4*)&Bs[kk][tx * 8 + 4];
            float ar[8] = {av0.x,av0.y,av0.z,av0.w,av1.x,av1.y,av1.z,av1.w};
            float br[8] = {bv0.x,bv0.y,bv0.z,bv0.w,bv1.x,bv1.y,bv1.z,bv1.w};
            #pragma unroll
            for (int i = 0; i < 8; i++)
                #pragma unroll
                for (int j = 0; j < 8; j++)
                    acc[i][j] = fmaf(ar[i], br[j], acc[i][j]);
        }
        __syncthreads();
    }
    #pragma unroll
    for (int i = 0; i < 8; i++) {
        long r = row0 + ty * 8 + i;
        #pragma unroll
        for (int j = 0; j < 8; j++) {
            long c = col0 + tx * 8 + j;
            float v = acc[i][j];
            if (bi)    v += bi[c];
            if (resid) v += resid[r * N + c];
            if (relu)  v  = fmaxf(v, 0.f);
            C[r * N + c] = v;
        }
    }
}

// ---------------- scores = (Q @ K^T) / sqrt(KD), causal block skip -----------
__global__ __launch_bounds__(256) void gemm_nt_causal(
    const float* __restrict__ Qg, const float* __restrict__ Kg,
    float* __restrict__ SCg, float scale)
{
    if (blockIdx.x > blockIdx.y) return;  // fully above diagonal: never read
    const float* A = Qg + (long)blockIdx.z * S * KD;
    const float* B = Kg + (long)blockIdx.z * S * KD;
    float*       C = SCg + (long)blockIdx.z * S * (long)S;

    __shared__ float As[BKT][BMT];
    __shared__ float Bs[BKT][BNT];

    const int tid = threadIdx.x;
    const long row0 = (long)blockIdx.y * BMT;
    const long col0 = (long)blockIdx.x * BNT;
    const int arow = tid >> 1, avec = (tid & 1) * 8;
    const int ty = tid >> 4, tx = tid & 15;

    float acc[8][8] = {};

    for (int k0 = 0; k0 < KD; k0 += BKT) {
        const float* ap = A + (row0 + arow) * (long)KD + k0 + avec;
        float4 a0 = *(const float4*)(ap);
        float4 a1 = *(const float4*)(ap + 4);
        As[avec + 0][arow] = a0.x; As[avec + 1][arow] = a0.y;
        As[avec + 2][arow] = a0.z; As[avec + 3][arow] = a0.w;
        As[avec + 4][arow] = a1.x; As[avec + 5][arow] = a1.y;
        As[avec + 6][arow] = a1.z; As[avec + 7][arow] = a1.w;
        const float* bp = B + (col0 + arow) * (long)KD + k0 + avec;
        float4 b0 = *(const float4*)(bp);
        float4 b1 = *(const float4*)(bp + 4);
        Bs[avec + 0][arow] = b0.x; Bs[avec + 1][arow] = b0.y;
        Bs[avec + 2][arow] = b0.z; Bs[avec + 3][arow] = b0.w;
        Bs[avec + 4][arow] = b1.x; Bs[avec + 5][arow] = b1.y;
        Bs[avec + 6][arow] = b1.z; Bs[avec + 7][arow] = b1.w;
        __syncthreads();
        #pragma unroll
        for (int kk = 0; kk < BKT; kk++) {
            float4 av0 = *(const float4*)&As[kk][ty * 8];
            float4 av1 = *(const float4*)&As[kk][ty * 8 + 4];
            float4 bv0 = *(const float4*)&Bs[kk][tx * 8];
            float4 bv1 = *(const float4*)&Bs[kk][tx * 8 + 4];
            float ar[8] = {av0.x,av0.y,av0.z,av0.w,av1.x,av1.y,av1.z,av1.w};
            float br[8] = {bv0.x,bv0.y,bv0.z,bv0.w,bv1.x,bv1.y,bv1.z,bv1.w};
            #pragma unroll
            for (int i = 0; i < 8; i++)
                #pragma unroll
                for (int j = 0; j < 8; j++)
                    acc[i][j] = fmaf(ar[i], br[j], acc[i][j]);
        }
        __syncthreads();
    }
    #pragma unroll
    for (int i = 0; i < 8; i++) {
        long r = row0 + ty * 8 + i;
        #pragma unroll
        for (int j = 0; j < 8; j++) {
            long c = col0 + tx * 8 + j;
            C[r * S + c] = acc[i][j] * scale;
        }
    }
}

// ---------------- causal row softmax, in place, zeros above diagonal ---------
__global__ __launch_bounds__(256) void softmax_causal(float* __restrict__ sc)
{
    const int s = blockIdx.x;
    const int h = blockIdx.y;
    float* row = sc + ((long)h * S + s) * (long)S;
    __shared__ float buf[S];
    __shared__ float red[256];
    const int tid = threadIdx.x;
    const int len = s + 1;

    float lmax = -INFINITY;
    for (int t = tid; t < len; t += 256) { float v = row[t]; buf[t] = v; lmax = fmaxf(lmax, v); }
    red[tid] = lmax; __syncthreads();
    for (int st = 128; st; st >>= 1) {
        if (tid < st) red[tid] = fmaxf(red[tid], red[tid + st]);
        __syncthreads();
    }
    const float m = red[0];
    __syncthreads();

    float lsum = 0.f;
    for (int t = tid; t < len; t += 256) { float e = __expf(buf[t] - m); buf[t] = e; lsum += e; }
    red[tid] = lsum; __syncthreads();
    for (int st = 128; st; st >>= 1) {
        if (tid < st) red[tid] += red[tid + st];
        __syncthreads();
    }
    const float inv = 1.f / red[0];
    for (int t = tid; t < S; t += 256) row[t] = (t < len) ? buf[t] * inv : 0.f;
}

// ---------------- attn_out[s,f] = x[s,f] + sum_h sum_t attn[h,s,t] v[h,t,f] --
// K-loop bounded at row_block_end (attn is exactly 0 above the diagonal).
__global__ __launch_bounds__(256) void attn_av(
    const float* __restrict__ ATT, const float* __restrict__ V,
    const float* __restrict__ X, float* __restrict__ C)
{
    __shared__ float As[BKT][BMT];
    __shared__ float Bs[BKT][BNT];
    const int tid = threadIdx.x;
    const long row0 = (long)blockIdx.y * BMT;
    const long col0 = (long)blockIdx.x * BNT;
    const int arow = tid >> 1, avec = (tid & 1) * 8;
    const int brow = tid >> 4, bcol = (tid & 15) * 8;
    const int ty = tid >> 4, tx = tid & 15;
    const int kmax = (int)row0 + BMT;

    float acc[8][8] = {};

    for (int h = 0; h < H; h++) {
        const float* A = ATT + (long)h * S * S;
        const float* B = V   + (long)h * S * E;
        for (int k0 = 0; k0 < kmax; k0 += BKT) {
            const float* ap = A + (row0 + arow) * (long)S + k0 + avec;
            float4 a0 = *(const float4*)(ap);
            float4 a1 = *(const float4*)(ap + 4);
            As[avec + 0][arow] = a0.x; As[avec + 1][arow] = a0.y;
            As[avec + 2][arow] = a0.z; As[avec + 3][arow] = a0.w;
            As[avec + 4][arow] = a1.x; As[avec + 5][arow] = a1.y;
            As[avec + 6][arow] = a1.z; As[avec + 7][arow] = a1.w;
            const float* bp = B + (long)(k0 + brow) * E + col0 + bcol;
            *(float4*)&Bs[brow][bcol + 0] = *(const float4*)(bp);
            *(float4*)&Bs[brow][bcol + 4] = *(const float4*)(bp + 4);
            __syncthreads();
            #pragma unroll
            for (int kk = 0; kk < BKT; kk++) {
                float4 av0 = *(const float4*)&As[kk][ty * 8];
                float4 av1 = *(const float4*)&As[kk][ty * 8 + 4];
                float4 bv0 = *(const float4*)&Bs[kk][tx * 8];
                float4 bv1 = *(const float4*)&Bs[kk][tx * 8 + 4];
                float ar[8] = {av0.x,av0.y,av0.z,av0.w,av1.x,av1.y,av1.z,av1.w};
                float br[8] = {bv0.x,bv0.y,bv0.z,bv0.w,bv1.x,bv1.y,bv1.z,bv1.w};
                #pragma unroll
                for (int i = 0; i < 8; i++)
                    #pragma unroll
                    for (int j = 0; j < 8; j++)
                        acc[i][j] = fmaf(ar[i], br[j], acc[i][j]);
            }
            __syncthreads();
        }
    }
    #pragma unroll
    for (int i = 0; i < 8; i++) {
        long r = row0 + ty * 8 + i;
        #pragma unroll
        for (int j = 0; j < 8; j++) {
            long c = col0 + tx * 8 + j;
            C[r * E + c] = X[r * E + c] + acc[i][j];
        }
    }
}

// ---------------- global LayerNorm (mean/var over ALL S*E elements) ----------
__global__ __launch_bounds__(256) void ln_reduce(const float* __restrict__ y,
                                                 double* __restrict__ part)
{
    __shared__ double sd[256], sq[256];
    double s = 0.0, ss = 0.0;
    const long stride = (long)gridDim.x * 256;
    for (long i = (long)blockIdx.x * 256 + threadIdx.x; i < NTOT; i += stride) {
        double v = (double)y[i]; s += v; ss += v * v;
    }
    sd[threadIdx.x] = s; sq[threadIdx.x] = ss; __syncthreads();
    for (int st = 128; st; st >>= 1) {
        if (threadIdx.x < st) {
            sd[threadIdx.x] += sd[threadIdx.x + st];
            sq[threadIdx.x] += sq[threadIdx.x + st];
        }
        __syncthreads();
    }
    if (threadIdx.x == 0) { part[blockIdx.x] = sd[0]; part[1024 + blockIdx.x] = sq[0]; }
}

__global__ __launch_bounds__(256) void ln_finalize(const double* __restrict__ part,
                                                   float* __restrict__ stats)
{
    __shared__ double sd[256], sq[256];
    double s = 0.0, ss = 0.0;
    for (int i = threadIdx.x; i < 1024; i += 256) { s += part[i]; ss += part[1024 + i]; }
    sd[threadIdx.x] = s; sq[threadIdx.x] = ss; __syncthreads();
    for (int st = 128; st; st >>= 1) {
        if (threadIdx.x < st) {
            sd[threadIdx.x] += sd[threadIdx.x + st];
            sq[threadIdx.x] += sq[threadIdx.x + st];
        }
        __syncthreads();
    }
    if (threadIdx.x == 0) {
        double mean = sd[0] / (double)NTOT;
        double var  = sq[0] / (double)NTOT - mean * mean;
        stats[0] = (float)mean;
        stats[1] = (float)(1.0 / sqrt(var + (double)EPS));
    }
}

__global__ __launch_bounds__(256) void ln_apply(
    const float* __restrict__ y, const float* __restrict__ g,
    const float* __restrict__ b, const float* __restrict__ st,
    float* __restrict__ o)
{
    const float m = st[0], is = st[1];
    const long stride = (long)gridDim.x * 256;
    for (long i = (long)blockIdx.x * 256 + threadIdx.x; i < NTOT; i += stride)
        o[i] = (y[i] - m) * is * g[i] + b[i];
}

// ---------------- host orchestration ----------------------------------------
extern "C" void kernel_launch(void* const* d_in, const int* in_sizes, int n_in,
                              void* d_out, int out_size)
{
    const float* x  = (const float*)d_in[0];
    const float* Wq = (const float*)d_in[1];
    const float* bq = (const float*)d_in[2];
    const float* Wk = (const float*)d_in[3];
    const float* bk = (const float*)d_in[4];
    const float* Wv = (const float*)d_in[5];
    const float* bv = (const float*)d_in[6];
    const float* lg = (const float*)d_in[7];
    const float* lb = (const float*)d_in[8];
    const float* W1 = (const float*)d_in[9];
    const float* b1 = (const float*)d_in[10];
    const float* W2 = (const float*)d_in[11];
    const float* b2 = (const float*)d_in[12];
    float* out = (float*)d_out;

    float *pq, *pk, *pv, *psc, *py, *ph, *pff, *pstats;
    double* ppart;
    cudaGetSymbolAddress((void**)&pq,  g_q);
    cudaGetSymbolAddress((void**)&pk,  g_k);
    cudaGetSymbolAddress((void**)&pv,  g_v);
    cudaGetSymbolAddress((void**)&psc, g_sc);
    cudaGetSymbolAddress((void**)&py,  g_y);
    cudaGetSymbolAddress((void**)&ph,  g_h);
    cudaGetSymbolAddress((void**)&pff, g_ff);
    cudaGetSymbolAddress((void**)&ppart,  g_part);
    cudaGetSymbolAddress((void**)&pstats, g_stats);

    dim3 blk(256);

    // Q/K/V projections (per-head GEMMs batched over blockIdx.z)
    gemm_nn<<<dim3(KD / BNT, S / BMT, H), blk>>>(x, Wq, bq, nullptr, pq,
        S, KD, E, (long)E * KD, (long)KD, (long)S * KD, 0);
    gemm_nn<<<dim3(KD / BNT, S / BMT, H), blk>>>(x, Wk, bk, nullptr, pk,
        S, KD, E, (long)E * KD, (long)KD, (long)S * KD, 0);
    gemm_nn<<<dim3(E / BNT, S / BMT, H), blk>>>(x, Wv, bv, nullptr, pv,
        S, E, E, (long)E * E, (long)E, (long)S * E, 0);

    // scores + causal softmax
    gemm_nt_causal<<<dim3(S / BNT, S / BMT, H), blk>>>(pq, pk, psc,
        1.0f / sqrtf((float)KD));
    softmax_causal<<<dim3(S, H), blk>>>(psc);

    // attn @ V, summed over heads, + residual x
    attn_av<<<dim3(E / BNT, S / BMT), blk>>>(psc, pv, x, py);

    // LN1 (global mean/var over whole [S,E])
    ln_reduce<<<1024, blk>>>(py, ppart);
    ln_finalize<<<1, blk>>>(ppart, pstats);
    ln_apply<<<4096, blk>>>(py, lg, lb, pstats, ph);

    // FFN
    gemm_nn<<<dim3(FF / BNT, S / BMT, 1), blk>>>(ph, W1, b1, nullptr, pff,
        S, FF, E, 0, 0, 0, 1);
    gemm_nn<<<dim3(E / BNT, S / BMT, 1), blk>>>(pff, W2, b2, ph, py,
        S, E, FF, 0, 0, 0, 0);

    // LN2 -> output
    ln_reduce<<<1024, blk>>>(py, ppart);
    ln_finalize<<<1, blk>>>(ppart, pstats);
    ln_apply<<<4096, blk>>>(py, lg, lb, pstats, out);
}

// round 9
// speedup vs baseline: 2.1844x; 2.1844x over previous
#include <cuda_runtime.h>
#include <cuda_bf16.h>
#include <stdint.h>
#include <math.h>

// Problem dims
#define S_DIM 2048
#define E_DIM 2048
#define H_DIM 16
#define KD_DIM 128
#define FF_DIM 8192
#define EPS 1e-5f
#define NTOT (2048L * 2048L)

// ---------------- scratch (device globals; no allocations allowed) ----------
__device__ float  g_q [(long)H_DIM * S_DIM * KD_DIM];
__device__ float  g_k [(long)H_DIM * S_DIM * KD_DIM];
__device__ float  g_v [(long)H_DIM * S_DIM * E_DIM];
__device__ float  g_sc[(long)H_DIM * S_DIM * S_DIM];
__device__ float  g_y [(long)S_DIM * E_DIM];
__device__ float  g_h [(long)S_DIM * E_DIM];
__device__ float  g_ff[(long)S_DIM * FF_DIM];
__device__ double g_part[2048];
__device__ float  g_stats[2];

// =====================  bf16-split tensor-core GEMM engine  =================
// Block tile 128x128, BK=16 (one m16n8k16 step per stage), 256 threads,
// warp grid 2(M) x 4(N), warp tile 64x32 -> 4x4 mma atoms per warp.
// A = Ah + Al, B = Bh + Bl (bf16 each); acc += AhBh + AhBl + AlBh.
// Double-buffered smem stages: one __syncthreads per k16 stage.
#define PITCH 136

struct SmemTiles {
    uint32_t AsH[8][PITCH];
    uint32_t AsL[8][PITCH];
    uint32_t BsH[8][PITCH];
    uint32_t BsL[8][PITCH];
};

__device__ __forceinline__ void split_pair(float f0, float f1,
                                           uint32_t &hi, uint32_t &lo)
{
    __nv_bfloat16 h0 = __float2bfloat16_rn(f0);
    __nv_bfloat16 h1 = __float2bfloat16_rn(f1);
    __nv_bfloat16 l0 = __float2bfloat16_rn(f0 - __bfloat162float(h0));
    __nv_bfloat16 l1 = __float2bfloat16_rn(f1 - __bfloat162float(h1));
    unsigned short u0 = __bfloat16_as_ushort(h0);
    unsigned short u1 = __bfloat16_as_ushort(h1);
    unsigned short w0 = __bfloat16_as_ushort(l0);
    unsigned short w1 = __bfloat16_as_ushort(l1);
    hi = (uint32_t)u0 | ((uint32_t)u1 << 16);
    lo = (uint32_t)w0 | ((uint32_t)w1 << 16);
}

__device__ __forceinline__ void mma16816(float *c, const uint32_t *a,
                                         const uint32_t *b)
{
    asm volatile(
        "mma.sync.aligned.m16n8k16.row.col.f32.bf16.bf16.f32 "
        "{%0,%1,%2,%3},{%4,%5,%6,%7},{%8,%9},{%0,%1,%2,%3};\n"
        : "+f"(c[0]), "+f"(c[1]), "+f"(c[2]), "+f"(c[3])
        : "r"(a[0]), "r"(a[1]), "r"(a[2]), "r"(a[3]), "r"(b[0]), "r"(b[1]));
}

// one k16 step for a 64x32 warp tile
__device__ __forceinline__ void compute_stage(const SmemTiles *sm,
    float acc[4][4][4], int m0w, int n0w, int g, int t)
{
    uint32_t bh[4][2];
    uint32_t bl[4][2];
    int na, ma;
    #pragma unroll
    for (na = 0; na < 4; na++) {
        int c = n0w + na * 8 + g;
        bh[na][0] = sm->BsH[t][c];
        bh[na][1] = sm->BsH[t + 4][c];
        bl[na][0] = sm->BsL[t][c];
        bl[na][1] = sm->BsL[t + 4][c];
    }
    #pragma unroll
    for (ma = 0; ma < 4; ma++) {
        int r0 = m0w + ma * 16 + g;
        uint32_t ah[4];
        uint32_t al[4];
        ah[0] = sm->AsH[t][r0];
        ah[1] = sm->AsH[t][r0 + 8];
        ah[2] = sm->AsH[t + 4][r0];
        ah[3] = sm->AsH[t + 4][r0 + 8];
        al[0] = sm->AsL[t][r0];
        al[1] = sm->AsL[t][r0 + 8];
        al[2] = sm->AsL[t + 4][r0];
        al[3] = sm->AsL[t + 4][r0 + 8];
        #pragma unroll
        for (na = 0; na < 4; na++) {
            mma16816(acc[ma][na], ah, bh[na]);
            mma16816(acc[ma][na], ah, bl[na]);
            mma16816(acc[ma][na], al, bh[na]);
        }
    }
}

// stage a row-major [128 x 16] tile "column-wise": thread owns row = tid>>1,
// k-halfword base = (tid&1)*8 floats; dest smem rows k2b..k2b+3
__device__ __forceinline__ void store_colstage(uint32_t (*Hi)[PITCH],
    uint32_t (*Lo)[PITCH], float4 v0, float4 v1, int k2b, int row)
{
    split_pair(v0.x, v0.y, Hi[k2b + 0][row], Lo[k2b + 0][row]);
    split_pair(v0.z, v0.w, Hi[k2b + 1][row], Lo[k2b + 1][row]);
    split_pair(v1.x, v1.y, Hi[k2b + 2][row], Lo[k2b + 2][row]);
    split_pair(v1.z, v1.w, Hi[k2b + 3][row], Lo[k2b + 3][row]);
}

// stage a row-major [16 x 128] B tile: thread owns k2 = tid>>5, col = (tid&31)*4
__device__ __forceinline__ void store_rowstage(SmemTiles *sm,
    float4 r0, float4 r1, int k2, int nc)
{
    uint32_t h0, h1, h2, h3, l0, l1, l2, l3;
    split_pair(r0.x, r1.x, h0, l0);
    split_pair(r0.y, r1.y, h1, l1);
    split_pair(r0.z, r1.z, h2, l2);
    split_pair(r0.w, r1.w, h3, l3);
    sm->BsH[k2][nc + 0] = h0;
    sm->BsH[k2][nc + 1] = h1;
    sm->BsH[k2][nc + 2] = h2;
    sm->BsH[k2][nc + 3] = h3;
    sm->BsL[k2][nc + 0] = l0;
    sm->BsL[k2][nc + 1] = l1;
    sm->BsL[k2][nc + 2] = l2;
    sm->BsL[k2][nc + 3] = l3;
}

// ---------------- C = A[M,K] @ B[K,N] (+bias)(+resid)(relu), batched z ------
__global__ void __launch_bounds__(256) mma_gemm_nn(
    const float *Ag, const float *Bg,
    const float *bias, const float *resid,
    float *Cg, int K, int N,
    long sB, long sBias, long sC, int relu)
{
    __shared__ SmemTiles sm[2];

    const float *A = Ag;
    const float *B = Bg + (long)blockIdx.z * sB;
    const float *bi = (bias != 0) ? (bias + (long)blockIdx.z * sBias) : (const float *)0;
    float *C = Cg + (long)blockIdx.z * sC;

    int tid = threadIdx.x;
    int lane = tid & 31;
    int warp = tid >> 5;
    int g = lane >> 2;
    int t = lane & 3;
    int m0w = (warp >> 2) * 64;
    int n0w = (warp & 3) * 32;
    long row0 = (long)blockIdx.y * 128;
    long col0 = (long)blockIdx.x * 128;

    int arow = tid >> 1;
    int akc = (tid & 1) * 8;
    int ak2 = (tid & 1) * 4;
    int bkr = tid >> 5;
    int bnc = (tid & 31) * 4;

    float acc[4][4][4];
    int i0, i1, i2;
    #pragma unroll
    for (i0 = 0; i0 < 4; i0++)
        #pragma unroll
        for (i1 = 0; i1 < 4; i1++)
            #pragma unroll
            for (i2 = 0; i2 < 4; i2++)
                acc[i0][i1][i2] = 0.0f;

    const float *aptr = A + (row0 + arow) * (long)K + akc;
    const float *bptr = B + (long)(2 * bkr) * N + col0 + bnc;

    float4 pa0 = *(const float4 *)(aptr);
    float4 pa1 = *(const float4 *)(aptr + 4);
    float4 pb0 = *(const float4 *)(bptr);
    float4 pb1 = *(const float4 *)(bptr + N);

    store_colstage(sm[0].AsH, sm[0].AsL, pa0, pa1, ak2, arow);
    store_rowstage(&sm[0], pb0, pb1, bkr, bnc);
    __syncthreads();

    int nsteps = K / 16;
    int s;
    for (s = 0; s < nsteps; s++) {
        int more = (s + 1 < nsteps) ? 1 : 0;
        if (more) {
            const float *ap2 = aptr + (s + 1) * 16;
            const float *bp2 = bptr + (long)(s + 1) * 16 * N;
            pa0 = *(const float4 *)(ap2);
            pa1 = *(const float4 *)(ap2 + 4);
            pb0 = *(const float4 *)(bp2);
            pb1 = *(const float4 *)(bp2 + N);
        }
        compute_stage(&sm[s & 1], acc, m0w, n0w, g, t);
        if (more) {
            store_colstage(sm[(s + 1) & 1].AsH, sm[(s + 1) & 1].AsL,
                           pa0, pa1, ak2, arow);
            store_rowstage(&sm[(s + 1) & 1], pb0, pb1, bkr, bnc);
            __syncthreads();
        }
    }

    int ma, na;
    #pragma unroll
    for (ma = 0; ma < 4; ma++) {
        long r = row0 + m0w + ma * 16 + g;
        #pragma unroll
        for (na = 0; na < 4; na++) {
            long c = col0 + n0w + na * 8 + 2 * t;
            float b0 = 0.0f;
            float b1 = 0.0f;
            if (bi != 0) {
                b0 = bi[c];
                b1 = bi[c + 1];
            }
            float v0 = acc[ma][na][0] + b0;
            float v1 = acc[ma][na][1] + b1;
            float w0 = acc[ma][na][2] + b0;
            float w1 = acc[ma][na][3] + b1;
            if (resid != 0) {
                v0 += resid[r * N + c];
                v1 += resid[r * N + c + 1];
                w0 += resid[(r + 8) * N + c];
                w1 += resid[(r + 8) * N + c + 1];
            }
            if (relu != 0) {
                v0 = fmaxf(v0, 0.0f);
                v1 = fmaxf(v1, 0.0f);
                w0 = fmaxf(w0, 0.0f);
                w1 = fmaxf(w1, 0.0f);
            }
            C[r * N + c]           = v0;
            C[r * N + c + 1]       = v1;
            C[(r + 8) * N + c]     = w0;
            C[(r + 8) * N + c + 1] = w1;
        }
    }
}

// ---------------- scores = (Q @ K^T)/sqrt(KD), causal block skip ------------
__global__ void __launch_bounds__(256) mma_gemm_nt_causal(
    const float *Qg, const float *Kg, float *SCg, float scale)
{
    __shared__ SmemTiles sm[2];

    if (blockIdx.x > blockIdx.y) return;
    const float *A = Qg + (long)blockIdx.z * S_DIM * KD_DIM;
    const float *B = Kg + (long)blockIdx.z * S_DIM * KD_DIM;
    float *C = SCg + (long)blockIdx.z * S_DIM * (long)S_DIM;

    int tid = threadIdx.x;
    int lane = tid & 31;
    int warp = tid >> 5;
    int g = lane >> 2;
    int t = lane & 3;
    int m0w = (warp >> 2) * 64;
    int n0w = (warp & 3) * 32;
    long row0 = (long)blockIdx.y * 128;
    long col0 = (long)blockIdx.x * 128;

    int arow = tid >> 1;
    int akc = (tid & 1) * 8;
    int ak2 = (tid & 1) * 4;

    float acc[4][4][4];
    int i0, i1, i2;
    #pragma unroll
    for (i0 = 0; i0 < 4; i0++)
        #pragma unroll
        for (i1 = 0; i1 < 4; i1++)
            #pragma unroll
            for (i2 = 0; i2 < 4; i2++)
                acc[i0][i1][i2] = 0.0f;

    const float *aptr = A + (row0 + arow) * (long)KD_DIM + akc;
    const float *bptr = B + (col0 + arow) * (long)KD_DIM + akc;

    float4 pa0 = *(const float4 *)(aptr);
    float4 pa1 = *(const float4 *)(aptr + 4);
    float4 pb0 = *(const float4 *)(bptr);
    float4 pb1 = *(const float4 *)(bptr + 4);

    store_colstage(sm[0].AsH, sm[0].AsL, pa0, pa1, ak2, arow);
    store_colstage(sm[0].BsH, sm[0].BsL, pb0, pb1, ak2, arow);
    __syncthreads();

    int nsteps = KD_DIM / 16;
    int s;
    for (s = 0; s < nsteps; s++) {
        int more = (s + 1 < nsteps) ? 1 : 0;
        if (more) {
            const float *ap2 = aptr + (s + 1) * 16;
            const float *bp2 = bptr + (s + 1) * 16;
            pa0 = *(const float4 *)(ap2);
            pa1 = *(const float4 *)(ap2 + 4);
            pb0 = *(const float4 *)(bp2);
            pb1 = *(const float4 *)(bp2 + 4);
        }
        compute_stage(&sm[s & 1], acc, m0w, n0w, g, t);
        if (more) {
            store_colstage(sm[(s + 1) & 1].AsH, sm[(s + 1) & 1].AsL,
                           pa0, pa1, ak2, arow);
            store_colstage(sm[(s + 1) & 1].BsH, sm[(s + 1) & 1].BsL,
                           pb0, pb1, ak2, arow);
            __syncthreads();
        }
    }

    int ma, na;
    #pragma unroll
    for (ma = 0; ma < 4; ma++) {
        long r = row0 + m0w + ma * 16 + g;
        #pragma unroll
        for (na = 0; na < 4; na++) {
            long c = col0 + n0w + na * 8 + 2 * t;
            C[r * S_DIM + c]           = acc[ma][na][0] * scale;
            C[r * S_DIM + c + 1]       = acc[ma][na][1] * scale;
            C[(r + 8) * S_DIM + c]     = acc[ma][na][2] * scale;
            C[(r + 8) * S_DIM + c + 1] = acc[ma][na][3] * scale;
        }
    }
}

// ---------------- attn_out = X + sum_h attn[h] @ V[h], bounded k ------------
__global__ void __launch_bounds__(256) mma_attn_av(
    const float *ATT, const float *V, const float *X, float *C)
{
    __shared__ SmemTiles sm[2];

    int tid = threadIdx.x;
    int lane = tid & 31;
    int warp = tid >> 5;
    int g = lane >> 2;
    int t = lane & 3;
    int m0w = (warp >> 2) * 64;
    int n0w = (warp & 3) * 32;
    long row0 = (long)blockIdx.y * 128;
    long col0 = (long)blockIdx.x * 128;

    int arow = tid >> 1;
    int akc = (tid & 1) * 8;
    int ak2 = (tid & 1) * 4;
    int bkr = tid >> 5;
    int bnc = (tid & 31) * 4;

    int nk = ((int)blockIdx.y + 1) * 8;   // k16 steps per head
    int total = H_DIM * nk;

    float acc[4][4][4];
    int i0, i1, i2;
    #pragma unroll
    for (i0 = 0; i0 < 4; i0++)
        #pragma unroll
        for (i1 = 0; i1 < 4; i1++)
            #pragma unroll
            for (i2 = 0; i2 < 4; i2++)
                acc[i0][i1][i2] = 0.0f;

    float4 pa0, pa1, pb0, pb1;
    const float *ap0 = ATT + (row0 + arow) * (long)S_DIM + akc;
    const float *bp0 = V + (long)(2 * bkr) * E_DIM + col0 + bnc;
    pa0 = *(const float4 *)(ap0);
    pa1 = *(const float4 *)(ap0 + 4);
    pb0 = *(const float4 *)(bp0);
    pb1 = *(const float4 *)(bp0 + E_DIM);

    store_colstage(sm[0].AsH, sm[0].AsL, pa0, pa1, ak2, arow);
    store_rowstage(&sm[0], pb0, pb1, bkr, bnc);
    __syncthreads();

    int h = 0;
    int ks = 0;
    int it;
    for (it = 0; it < total; it++) {
        int more = (it + 1 < total) ? 1 : 0;
        int h2 = h;
        int k2 = ks + 1;
        if (k2 == nk) {
            k2 = 0;
            h2 = h2 + 1;
        }
        if (more) {
            const float *ap2 = ATT + (long)h2 * S_DIM * S_DIM
                             + (row0 + arow) * (long)S_DIM + k2 * 16 + akc;
            const float *bp2 = V + (long)h2 * S_DIM * E_DIM
                             + (long)(k2 * 16 + 2 * bkr) * E_DIM + col0 + bnc;
            pa0 = *(const float4 *)(ap2);
            pa1 = *(const float4 *)(ap2 + 4);
            pb0 = *(const float4 *)(bp2);
            pb1 = *(const float4 *)(bp2 + E_DIM);
        }
        compute_stage(&sm[it & 1], acc, m0w, n0w, g, t);
        if (more) {
            store_colstage(sm[(it + 1) & 1].AsH, sm[(it + 1) & 1].AsL,
                           pa0, pa1, ak2, arow);
            store_rowstage(&sm[(it + 1) & 1], pb0, pb1, bkr, bnc);
            __syncthreads();
        }
        h = h2;
        ks = k2;
    }

    int ma, na;
    #pragma unroll
    for (ma = 0; ma < 4; ma++) {
        long r = row0 + m0w + ma * 16 + g;
        #pragma unroll
        for (na = 0; na < 4; na++) {
            long c = col0 + n0w + na * 8 + 2 * t;
            C[r * E_DIM + c]           = acc[ma][na][0] + X[r * E_DIM + c];
            C[r * E_DIM + c + 1]       = acc[ma][na][1] + X[r * E_DIM + c + 1];
            C[(r + 8) * E_DIM + c]     = acc[ma][na][2] + X[(r + 8) * E_DIM + c];
            C[(r + 8) * E_DIM + c + 1] = acc[ma][na][3] + X[(r + 8) * E_DIM + c + 1];
        }
    }
}

// ---------------- causal row softmax, in place, zeros above diagonal --------
__global__ void __launch_bounds__(256) softmax_causal(float *sc)
{
    __shared__ float buf[S_DIM];
    __shared__ float red[256];

    int s = blockIdx.x;
    int h = blockIdx.y;
    float *row = sc + ((long)h * S_DIM + s) * (long)S_DIM;
    int tid = threadIdx.x;
    int len = s + 1;
    int i;
    int st;

    float lmax = -INFINITY;
    for (i = tid; i < len; i += 256) {
        float v = row[i];
        buf[i] = v;
        lmax = fmaxf(lmax, v);
    }
    red[tid] = lmax;
    __syncthreads();
    for (st = 128; st > 0; st >>= 1) {
        if (tid < st) red[tid] = fmaxf(red[tid], red[tid + st]);
        __syncthreads();
    }
    float m = red[0];
    __syncthreads();

    float lsum = 0.0f;
    for (i = tid; i < len; i += 256) {
        float e = __expf(buf[i] - m);
        buf[i] = e;
        lsum += e;
    }
    red[tid] = lsum;
    __syncthreads();
    for (st = 128; st > 0; st >>= 1) {
        if (tid < st) red[tid] = red[tid] + red[tid + st];
        __syncthreads();
    }
    float inv = 1.0f / red[0];
    for (i = tid; i < S_DIM; i += 256) {
        float o = 0.0f;
        if (i < len) o = buf[i] * inv;
        row[i] = o;
    }
}

// ---------------- global LayerNorm (mean/var over ALL S*E elements) ---------
__global__ void __launch_bounds__(256) ln_reduce(const float *y, double *part)
{
    __shared__ double sd[256];
    __shared__ double sq[256];

    double s = 0.0;
    double ss = 0.0;
    long stride = (long)gridDim.x * 256;
    long i;
    int st;
    for (i = (long)blockIdx.x * 256 + threadIdx.x; i < NTOT; i += stride) {
        double v = (double)y[i];
        s += v;
        ss += v * v;
    }
    sd[threadIdx.x] = s;
    sq[threadIdx.x] = ss;
    __syncthreads();
    for (st = 128; st > 0; st >>= 1) {
        if (threadIdx.x < st) {
            sd[threadIdx.x] = sd[threadIdx.x] + sd[threadIdx.x + st];
            sq[threadIdx.x] = sq[threadIdx.x] + sq[threadIdx.x + st];
        }
        __syncthreads();
    }
    if (threadIdx.x == 0) {
        part[blockIdx.x] = sd[0];
        part[1024 + blockIdx.x] = sq[0];
    }
}

__global__ void __launch_bounds__(256) ln_finalize(const double *part, float *stats)
{
    __shared__ double sd[256];
    __shared__ double sq[256];

    double s = 0.0;
    double ss = 0.0;
    int i;
    int st;
    for (i = threadIdx.x; i < 1024; i += 256) {
        s += part[i];
        ss += part[1024 + i];
    }
    sd[threadIdx.x] = s;
    sq[threadIdx.x] = ss;
    __syncthreads();
    for (st = 128; st > 0; st >>= 1) {
        if (threadIdx.x < st) {
            sd[threadIdx.x] = sd[threadIdx.x] + sd[threadIdx.x + st];
            sq[threadIdx.x] = sq[threadIdx.x] + sq[threadIdx.x + st];
        }
        __syncthreads();
    }
    if (threadIdx.x == 0) {
        double mean = sd[0] / (double)NTOT;
        double var = sq[0] / (double)NTOT - mean * mean;
        stats[0] = (float)mean;
        stats[1] = (float)(1.0 / sqrt(var + (double)EPS));
    }
}

__global__ void __launch_bounds__(256) ln_apply(
    const float *y, const float *g, const float *b,
    const float *st, float *o)
{
    float m = st[0];
    float is = st[1];
    long stride = (long)gridDim.x * 256;
    long i;
    for (i = (long)blockIdx.x * 256 + threadIdx.x; i < NTOT; i += stride) {
        o[i] = (y[i] - m) * is * g[i] + b[i];
    }
}

// ---------------- host orchestration ----------------------------------------
extern "C" void kernel_launch(void* const* d_in, const int* in_sizes, int n_in,
                              void* d_out, int out_size)
{
    const float *x  = (const float *)d_in[0];
    const float *Wq = (const float *)d_in[1];
    const float *bq = (const float *)d_in[2];
    const float *Wk = (const float *)d_in[3];
    const float *bk = (const float *)d_in[4];
    const float *Wv = (const float *)d_in[5];
    const float *bv = (const float *)d_in[6];
    const float *lg = (const float *)d_in[7];
    const float *lb = (const float *)d_in[8];
    const float *W1 = (const float *)d_in[9];
    const float *b1 = (const float *)d_in[10];
    const float *W2 = (const float *)d_in[11];
    const float *b2 = (const float *)d_in[12];
    float *out = (float *)d_out;

    void *vq = 0;
    void *vk = 0;
    void *vv = 0;
    void *vsc = 0;
    void *vy = 0;
    void *vh = 0;
    void *vff = 0;
    void *vpart = 0;
    void *vstats = 0;
    cudaGetSymbolAddress(&vq,  g_q);
    cudaGetSymbolAddress(&vk,  g_k);
    cudaGetSymbolAddress(&vv,  g_v);
    cudaGetSymbolAddress(&vsc, g_sc);
    cudaGetSymbolAddress(&vy,  g_y);
    cudaGetSymbolAddress(&vh,  g_h);
    cudaGetSymbolAddress(&vff, g_ff);
    cudaGetSymbolAddress(&vpart,  g_part);
    cudaGetSymbolAddress(&vstats, g_stats);
    float *pq = (float *)vq;
    float *pk = (float *)vk;
    float *pv = (float *)vv;
    float *psc = (float *)vsc;
    float *py = (float *)vy;
    float *ph = (float *)vh;
    float *pff = (float *)vff;
    double *ppart = (double *)vpart;
    float *pstats = (float *)vstats;

    dim3 blk(256, 1, 1);
    float scale = 1.0f / sqrtf((float)KD_DIM);

    // Q/K/V projections (per-head, batched over blockIdx.z)
    {
        dim3 gq(1, S_DIM / 128, H_DIM);
        mma_gemm_nn<<<gq, blk>>>(x, Wq, bq, (const float *)0, pq,
            E_DIM, KD_DIM, (long)E_DIM * KD_DIM, (long)KD_DIM,
            (long)S_DIM * KD_DIM, 0);
        mma_gemm_nn<<<gq, blk>>>(x, Wk, bk, (const float *)0, pk,
            E_DIM, KD_DIM, (long)E_DIM * KD_DIM, (long)KD_DIM,
            (long)S_DIM * KD_DIM, 0);
    }
    {
        dim3 gv(E_DIM / 128, S_DIM / 128, H_DIM);
        mma_gemm_nn<<<gv, blk>>>(x, Wv, bv, (const float *)0, pv,
            E_DIM, E_DIM, (long)E_DIM * E_DIM, (long)E_DIM,
            (long)S_DIM * E_DIM, 0);
    }

    // scores + causal softmax
    {
        dim3 gs(S_DIM / 128, S_DIM / 128, H_DIM);
        mma_gemm_nt_causal<<<gs, blk>>>(pq, pk, psc, scale);
    }
    {
        dim3 gsm(S_DIM, H_DIM, 1);
        softmax_causal<<<gsm, blk>>>(psc);
    }

    // attn @ V summed over heads, + residual x
    {
        dim3 ga(E_DIM / 128, S_DIM / 128, 1);
        mma_attn_av<<<ga, blk>>>(psc, pv, x, py);
    }

    // LN1 (global)
    ln_reduce<<<1024, blk>>>(py, ppart);
    ln_finalize<<<1, blk>>>(ppart, pstats);
    ln_apply<<<4096, blk>>>(py, lg, lb, pstats, ph);

    // FFN
    {
        dim3 g1(FF_DIM / 128, S_DIM / 128, 1);
        mma_gemm_nn<<<g1, blk>>>(ph, W1, b1, (const float *)0, pff,
            E_DIM, FF_DIM, 0L, 0L, 0L, 1);
        dim3 g2(E_DIM / 128, S_DIM / 128, 1);
        mma_gemm_nn<<<g2, blk>>>(pff, W2, b2, ph, py,
            FF_DIM, E_DIM, 0L, 0L, 0L, 0);
    }

    // LN2 -> output
    ln_reduce<<<1024, blk>>>(py, ppart);
    ln_finalize<<<1, blk>>>(ppart, pstats);
    ln_apply<<<4096, blk>>>(py, lg, lb, pstats, out);
}